// round 2
// baseline (speedup 1.0000x reference)
#include <cuda_runtime.h>
#include <math_constants.h>

// Problem constants
#define PB 4
#define PT 2048
#define PC 1024
#define PH 16
#define PDK 64
#define NTOK (PB * PT)      // 8192
#define M3 (3 * PC)         // 3072

// Scratch: q,k,v in [B,H,T,dk] layout; y in [B,T,C] layout
__device__ float g_q[NTOK * PC];
__device__ float g_k[NTOK * PC];
__device__ float g_v[NTOK * PC];
__device__ float g_y[NTOK * PC];

// ---------------------------------------------------------------------------
// QKV GEMM: qkv[n,m] = sum_k x[n,k] * w[m,k] + bias[m], scatter to q/k/v
// 64x64 tile, BK=32, 256 threads, 4x4 register tile per thread.
// ---------------------------------------------------------------------------
__global__ __launch_bounds__(256) void qkv_gemm_kernel(
    const float* __restrict__ x, const float* __restrict__ w,
    const float* __restrict__ bias)
{
    __shared__ float As[32][68];   // [k][n]
    __shared__ float Bs[32][68];   // [k][m]
    const int tid = threadIdx.x;
    const int tx = tid & 15, ty = tid >> 4;
    const int m0 = blockIdx.x * 64;
    const int n0 = blockIdx.y * 64;
    const int lr = tid >> 3;          // 0..31
    const int lc = (tid & 7) << 2;    // 0,4,...,28

    float acc[4][4] = {};
    for (int k0 = 0; k0 < PC; k0 += 32) {
        #pragma unroll
        for (int hh = 0; hh < 2; hh++) {
            const int row = lr + hh * 32;
            float4 a4 = *(const float4*)(x + (size_t)(n0 + row) * PC + k0 + lc);
            As[lc + 0][row] = a4.x;
            As[lc + 1][row] = a4.y;
            As[lc + 2][row] = a4.z;
            As[lc + 3][row] = a4.w;
            float4 b4 = *(const float4*)(w + (size_t)(m0 + row) * PC + k0 + lc);
            Bs[lc + 0][row] = b4.x;
            Bs[lc + 1][row] = b4.y;
            Bs[lc + 2][row] = b4.z;
            Bs[lc + 3][row] = b4.w;
        }
        __syncthreads();
        #pragma unroll
        for (int kk = 0; kk < 32; kk++) {
            float4 a4 = *(const float4*)&As[kk][ty << 2];
            float4 b4 = *(const float4*)&Bs[kk][tx << 2];
            float a[4] = {a4.x, a4.y, a4.z, a4.w};
            float b[4] = {b4.x, b4.y, b4.z, b4.w};
            #pragma unroll
            for (int i = 0; i < 4; i++)
                #pragma unroll
                for (int j = 0; j < 4; j++)
                    acc[i][j] = fmaf(a[i], b[j], acc[i][j]);
        }
        __syncthreads();
    }
    #pragma unroll
    for (int i = 0; i < 4; i++) {
        const int n = n0 + (ty << 2) + i;
        const int bidx = n / PT, tok = n % PT;
        #pragma unroll
        for (int j = 0; j < 4; j++) {
            const int m = m0 + (tx << 2) + j;
            const float val = acc[i][j] + bias[m];
            const int sec = m >> 10;          // 0=q, 1=k, 2=v
            const int c = m & (PC - 1);
            const int hh = c >> 6, d = c & 63;
            float* dst = (sec == 0) ? g_q : (sec == 1) ? g_k : g_v;
            dst[(((size_t)bidx * PH + hh) * PT + tok) * PDK + d] = val;
        }
    }
}

// ---------------------------------------------------------------------------
// Flash attention: one block per (q-tile, head, batch). Br=Bc=64, dk=64.
// 256 threads; thread (tx,ty) owns 4 rows x 4 cols of the 64x64 S tile and
// 4 rows x 4 d-cols of the O accumulator. Row state (m,l) replicated across
// the 16 tx-lanes (contiguous lanes -> warp shuffle reductions).
// ---------------------------------------------------------------------------
#define ATT_SMEM_FLOATS (64 * 68 * 2 + 64 * 64 * 2)

__global__ __launch_bounds__(256) void attn_kernel()
{
    extern __shared__ float sm[];
    float* Qt = sm;                 // [d][r], ld 68 (Q pre-scaled by 1/sqrt(dk))
    float* Kt = Qt + 64 * 68;       // [d][c], ld 68
    float* Vs = Kt + 64 * 68;       // [j][d], ld 64
    float* Pt = Vs + 64 * 64;       // [r][c], ld 64

    const int qt = blockIdx.x, hh = blockIdx.y, bidx = blockIdx.z;
    const float* qbase = g_q + (((size_t)bidx * PH + hh) * PT + qt * 64) * PDK;
    const float* kbase = g_k + (((size_t)bidx * PH + hh) * PT) * PDK;
    const float* vbase = g_v + (((size_t)bidx * PH + hh) * PT) * PDK;

    const int tid = threadIdx.x;
    const int tx = tid & 15, ty = tid >> 4;
    const int lj = tid >> 2;               // 0..63 (load row)
    const int ld0 = (tid & 3) << 4;        // 0,16,32,48 (load d-chunk)

    // Load Q tile, transposed, pre-scaled.
    #pragma unroll
    for (int i = 0; i < 4; i++) {
        float4 t4 = *(const float4*)(qbase + (size_t)lj * PDK + ld0 + i * 4);
        const int d = ld0 + i * 4;
        Qt[(d + 0) * 68 + lj] = t4.x * 0.125f;
        Qt[(d + 1) * 68 + lj] = t4.y * 0.125f;
        Qt[(d + 2) * 68 + lj] = t4.z * 0.125f;
        Qt[(d + 3) * 68 + lj] = t4.w * 0.125f;
    }

    float mrow[4], lrow[4], o[4][4];
    #pragma unroll
    for (int i = 0; i < 4; i++) {
        mrow[i] = -CUDART_INF_F;
        lrow[i] = 0.0f;
        #pragma unroll
        for (int j = 0; j < 4; j++) o[i][j] = 0.0f;
    }

    for (int kt = 0; kt < PT / 64; kt++) {
        __syncthreads();   // previous PV done reading Vs/Pt
        // Load K (transposed) and V (natural) tiles
        #pragma unroll
        for (int i = 0; i < 4; i++) {
            float4 t4 = *(const float4*)(kbase + ((size_t)kt * 64 + lj) * PDK + ld0 + i * 4);
            const int d = ld0 + i * 4;
            Kt[(d + 0) * 68 + lj] = t4.x;
            Kt[(d + 1) * 68 + lj] = t4.y;
            Kt[(d + 2) * 68 + lj] = t4.z;
            Kt[(d + 3) * 68 + lj] = t4.w;
            float4 v4 = *(const float4*)(vbase + ((size_t)kt * 64 + lj) * PDK + ld0 + i * 4);
            *(float4*)&Vs[lj * 64 + ld0 + i * 4] = v4;
        }
        __syncthreads();

        // S = (Q*scale) K^T   (4x4 per thread)
        float s[4][4] = {};
        #pragma unroll
        for (int d = 0; d < 64; d++) {
            float4 a4 = *(const float4*)&Qt[d * 68 + (ty << 2)];
            float4 b4 = *(const float4*)&Kt[d * 68 + (tx << 2)];
            float a[4] = {a4.x, a4.y, a4.z, a4.w};
            float b[4] = {b4.x, b4.y, b4.z, b4.w};
            #pragma unroll
            for (int i = 0; i < 4; i++)
                #pragma unroll
                for (int j = 0; j < 4; j++)
                    s[i][j] = fmaf(a[i], b[j], s[i][j]);
        }

        // Online softmax per row (16 tx-lanes = contiguous lanes of a warp half)
        #pragma unroll
        for (int i = 0; i < 4; i++) {
            float mx = fmaxf(fmaxf(s[i][0], s[i][1]), fmaxf(s[i][2], s[i][3]));
            #pragma unroll
            for (int off = 8; off >= 1; off >>= 1)
                mx = fmaxf(mx, __shfl_xor_sync(0xffffffffu, mx, off));
            const float mnew = fmaxf(mrow[i], mx);
            const float alpha = __expf(mrow[i] - mnew);
            mrow[i] = mnew;
            float rs = 0.0f;
            #pragma unroll
            for (int j = 0; j < 4; j++) {
                const float p = __expf(s[i][j] - mnew);
                s[i][j] = p;
                rs += p;
            }
            #pragma unroll
            for (int off = 8; off >= 1; off >>= 1)
                rs += __shfl_xor_sync(0xffffffffu, rs, off);
            lrow[i] = lrow[i] * alpha + rs;
            #pragma unroll
            for (int j = 0; j < 4; j++) o[i][j] *= alpha;
        }

        // Store P (natural layout), then O += P V
        #pragma unroll
        for (int i = 0; i < 4; i++) {
            float4 p4 = make_float4(s[i][0], s[i][1], s[i][2], s[i][3]);
            *(float4*)&Pt[((ty << 2) + i) * 64 + (tx << 2)] = p4;
        }
        __syncthreads();

        #pragma unroll
        for (int j = 0; j < 64; j++) {
            float4 v4 = *(const float4*)&Vs[j * 64 + (tx << 2)];
            float v[4] = {v4.x, v4.y, v4.z, v4.w};
            float p0 = Pt[((ty << 2) + 0) * 64 + j];
            float p1 = Pt[((ty << 2) + 1) * 64 + j];
            float p2 = Pt[((ty << 2) + 2) * 64 + j];
            float p3 = Pt[((ty << 2) + 3) * 64 + j];
            #pragma unroll
            for (int c = 0; c < 4; c++) {
                o[0][c] = fmaf(p0, v[c], o[0][c]);
                o[1][c] = fmaf(p1, v[c], o[1][c]);
                o[2][c] = fmaf(p2, v[c], o[2][c]);
                o[3][c] = fmaf(p3, v[c], o[3][c]);
            }
        }
    }

    // Normalize and write y in [B,T,C] layout (C = H*dk, head hh at offset hh*64)
    #pragma unroll
    for (int i = 0; i < 4; i++) {
        const float inv = 1.0f / lrow[i];
        const int tok = qt * 64 + (ty << 2) + i;
        float4 r4 = make_float4(o[i][0] * inv, o[i][1] * inv, o[i][2] * inv, o[i][3] * inv);
        *(float4*)&g_y[((size_t)bidx * PT + tok) * PC + hh * PDK + (tx << 2)] = r4;
    }
}

// ---------------------------------------------------------------------------
// Output projection: out[n,m] = sum_k y[n,k] * w_proj[m,k] + b_proj[m]
// ---------------------------------------------------------------------------
__global__ __launch_bounds__(256) void proj_gemm_kernel(
    const float* __restrict__ w, const float* __restrict__ bias,
    float* __restrict__ out)
{
    __shared__ float As[32][68];
    __shared__ float Bs[32][68];
    const int tid = threadIdx.x;
    const int tx = tid & 15, ty = tid >> 4;
    const int m0 = blockIdx.x * 64;
    const int n0 = blockIdx.y * 64;
    const int lr = tid >> 3;
    const int lc = (tid & 7) << 2;

    float acc[4][4] = {};
    for (int k0 = 0; k0 < PC; k0 += 32) {
        #pragma unroll
        for (int hh = 0; hh < 2; hh++) {
            const int row = lr + hh * 32;
            float4 a4 = *(const float4*)(g_y + (size_t)(n0 + row) * PC + k0 + lc);
            As[lc + 0][row] = a4.x;
            As[lc + 1][row] = a4.y;
            As[lc + 2][row] = a4.z;
            As[lc + 3][row] = a4.w;
            float4 b4 = *(const float4*)(w + (size_t)(m0 + row) * PC + k0 + lc);
            Bs[lc + 0][row] = b4.x;
            Bs[lc + 1][row] = b4.y;
            Bs[lc + 2][row] = b4.z;
            Bs[lc + 3][row] = b4.w;
        }
        __syncthreads();
        #pragma unroll
        for (int kk = 0; kk < 32; kk++) {
            float4 a4 = *(const float4*)&As[kk][ty << 2];
            float4 b4 = *(const float4*)&Bs[kk][tx << 2];
            float a[4] = {a4.x, a4.y, a4.z, a4.w};
            float b[4] = {b4.x, b4.y, b4.z, b4.w};
            #pragma unroll
            for (int i = 0; i < 4; i++)
                #pragma unroll
                for (int j = 0; j < 4; j++)
                    acc[i][j] = fmaf(a[i], b[j], acc[i][j]);
        }
        __syncthreads();
    }
    #pragma unroll
    for (int i = 0; i < 4; i++) {
        const int n = n0 + (ty << 2) + i;
        #pragma unroll
        for (int j = 0; j < 4; j++) {
            const int m = m0 + (tx << 2) + j;
            out[(size_t)n * PC + m] = acc[i][j] + bias[m];
        }
    }
}

// ---------------------------------------------------------------------------
extern "C" void kernel_launch(void* const* d_in, const int* in_sizes, int n_in,
                              void* d_out, int out_size)
{
    const float* x      = (const float*)d_in[0];
    const float* w_attn = (const float*)d_in[1];
    const float* b_attn = (const float*)d_in[2];
    const float* w_proj = (const float*)d_in[3];
    const float* b_proj = (const float*)d_in[4];
    float* out = (float*)d_out;

    static_assert(ATT_SMEM_FLOATS * 4 == 67584, "smem layout");
    cudaFuncSetAttribute(attn_kernel,
                         cudaFuncAttributeMaxDynamicSharedMemorySize,
                         ATT_SMEM_FLOATS * 4);

    dim3 g1(M3 / 64, NTOK / 64);   // 48 x 128
    qkv_gemm_kernel<<<g1, 256>>>(x, w_attn, b_attn);

    dim3 g2(PT / 64, PH, PB);      // 32 x 16 x 4
    attn_kernel<<<g2, 256, ATT_SMEM_FLOATS * 4>>>();

    dim3 g3(PC / 64, NTOK / 64);   // 16 x 128
    proj_gemm_kernel<<<g3, 256>>>(w_proj, b_proj, out);
}